// round 13
// baseline (speedup 1.0000x reference)
#include <cuda_runtime.h>
#include <math.h>

#define F 64
#define NEG 0.2f

static const int NMAX  = 50000;
static const int EMAX  = 800000;
static const int E2MAX = NMAX + EMAX;

// Scratch (allocation-free: __device__ globals)
__device__ __align__(128) float g_h [NMAX * F];   // h of current layer
__device__ __align__(128) float g_x1[NMAX * F];   // layer-1 output (pre-relu, bias added)
__device__ __align__(128) float g_asrc[NMAX];
__device__ __align__(128) float g_adst[NMAX];
__device__ __align__(128) float g_s[NMAX];
__device__ __align__(128) float g_w[E2MAX];
__device__ int g_is64;

// ---------------------------------------------------------------------------
// Detect whether edge_index is int64 or int32 (JAX x64-default ambiguity).
// In int64 little-endian, every odd int32 word of nonneg indices is 0.
// ---------------------------------------------------------------------------
__global__ void detect_kernel(const int* __restrict__ ei32) {
    if (blockIdx.x == 0 && threadIdx.x == 0) {
        int nz = 0;
        #pragma unroll 8
        for (int i = 0; i < 64; i++) nz += (ei32[2 * i + 1] != 0);
        g_is64 = (nz == 0) ? 1 : 0;
    }
}

__device__ __forceinline__ void load_edge(const void* ei, int idx, int E, int n,
                                          bool is64, int& src, int& dst) {
    if (idx < E) {
        if (is64) {
            const long long* p = (const long long*)ei;
            src = (int)p[idx];
            dst = (int)p[E + idx];
        } else {
            const int* p = (const int*)ei;
            src = p[idx];
            dst = p[E + idx];
        }
    } else {
        src = dst = idx - E;   // self loop
    }
}

// ---------------------------------------------------------------------------
// init: out[node][c] = bias[c]; s[node] = 0
// ---------------------------------------------------------------------------
__global__ void init_kernel(float* __restrict__ out, const float* __restrict__ bias, int n) {
    int idx = blockIdx.x * blockDim.x + threadIdx.x;
    if (idx < n * F) out[idx] = bias[idx & (F - 1)];
    if (idx < n) g_s[idx] = 0.f;
}

// ---------------------------------------------------------------------------
// Fused GEMM + attention scores.
// Block: 64 nodes x 64 cols, 256 threads, 4x4 register tile per thread.
// Xs padded stride K+4 (= 4 mod 32) -> conflict-free x broadcasts.
// Epilogue: h store + per-node dot with att_src/att_dst via 16-lane shfl reduce.
// ---------------------------------------------------------------------------
template<int K, bool RELU>
__global__ void __launch_bounds__(256) gemm_att_kernel(
    const float* __restrict__ X, const float* __restrict__ Wm,
    const float* __restrict__ att_s, const float* __restrict__ att_d,
    float* __restrict__ H, float* __restrict__ asrc, float* __restrict__ adst,
    int n)
{
    constexpr int XS = K + 4;
    __shared__ float Xs[64 * XS];
    __shared__ float Ws[32 * F];

    const int tid = threadIdx.x;
    const int nb  = blockIdx.x * 64;

    // Stage X tile (full K), vectorized + coalesced
    constexpr int K4 = K / 4;
    for (int i = tid; i < 64 * K4; i += 256) {
        int node = i / K4;
        int k4   = i - node * K4;
        int gn   = nb + node;
        float4 v = make_float4(0.f, 0.f, 0.f, 0.f);
        if (gn < n) {
            v = __ldg((const float4*)(X + (size_t)gn * K) + k4);
            if (RELU) {
                v.x = fmaxf(v.x, 0.f); v.y = fmaxf(v.y, 0.f);
                v.z = fmaxf(v.z, 0.f); v.w = fmaxf(v.w, 0.f);
            }
        }
        *(float4*)(Xs + node * XS + k4 * 4) = v;
    }

    const int cg = tid & 15, ng = tid >> 4;
    const int c0 = cg * 4, n0 = ng * 4;

    float acc[4][4];
    #pragma unroll
    for (int i = 0; i < 4; i++)
        #pragma unroll
        for (int j = 0; j < 4; j++) acc[i][j] = 0.f;

    for (int kt = 0; kt < K; kt += 32) {
        __syncthreads();                       // Xs staged / prev tile consumed
        for (int i = tid; i < 32 * F / 4; i += 256)
            ((float4*)Ws)[i] = __ldg((const float4*)(Wm + (size_t)kt * F) + i);
        __syncthreads();

        #pragma unroll
        for (int kk = 0; kk < 32; kk++) {
            float4 wv = *(const float4*)(Ws + kk * F + c0);
            int k = kt + kk;
            float x0 = Xs[(n0 + 0) * XS + k];
            float x1 = Xs[(n0 + 1) * XS + k];
            float x2 = Xs[(n0 + 2) * XS + k];
            float x3 = Xs[(n0 + 3) * XS + k];
            acc[0][0] += x0 * wv.x; acc[0][1] += x0 * wv.y; acc[0][2] += x0 * wv.z; acc[0][3] += x0 * wv.w;
            acc[1][0] += x1 * wv.x; acc[1][1] += x1 * wv.y; acc[1][2] += x1 * wv.z; acc[1][3] += x1 * wv.w;
            acc[2][0] += x2 * wv.x; acc[2][1] += x2 * wv.y; acc[2][2] += x2 * wv.z; acc[2][3] += x2 * wv.w;
            acc[3][0] += x3 * wv.x; acc[3][1] += x3 * wv.y; acc[3][2] += x3 * wv.z; acc[3][3] += x3 * wv.w;
        }
    }

    // Epilogue: store h, fused attention dots
    float4 av = __ldg((const float4*)att_s + cg);
    float4 dv = __ldg((const float4*)att_d + cg);
    #pragma unroll
    for (int i = 0; i < 4; i++) {
        int gn = nb + n0 + i;
        float ps = acc[i][0] * av.x + acc[i][1] * av.y + acc[i][2] * av.z + acc[i][3] * av.w;
        float pd = acc[i][0] * dv.x + acc[i][1] * dv.y + acc[i][2] * dv.z + acc[i][3] * dv.w;
        #pragma unroll
        for (int off = 8; off >= 1; off >>= 1) {
            ps += __shfl_xor_sync(0xffffffffu, ps, off);
            pd += __shfl_xor_sync(0xffffffffu, pd, off);
        }
        if (gn < n) {
            *(float4*)(H + (size_t)gn * F + c0) =
                make_float4(acc[i][0], acc[i][1], acc[i][2], acc[i][3]);
            if (cg == 0) { asrc[gn] = ps; adst[gn] = pd; }
        }
    }
}

// ---------------------------------------------------------------------------
// Edge pass A: w = exp(leaky_relu(a_src[src] + a_dst[dst])); s[dst] += w
// (segment-max dropped: algebraically identical softmax, values fp32-safe)
// ---------------------------------------------------------------------------
__global__ void edge_attn_kernel(const void* __restrict__ ei, int E, int n) {
    int idx = blockIdx.x * blockDim.x + threadIdx.x;
    int e2 = E + n;
    if (idx >= e2) return;
    bool is64 = (g_is64 != 0);
    int src, dst;
    load_edge(ei, idx, E, n, is64, src, dst);
    float e = g_asrc[src] + g_adst[dst];
    e = (e > 0.f) ? e : NEG * e;
    float w = __expf(e);
    g_w[idx] = w;
    atomicAdd(&g_s[dst], w);
}

// ---------------------------------------------------------------------------
// Edge pass B: out[dst][:] += (w/(s[dst]+eps)) * h[src][:]
// Half-warp (16 lanes) per edge, float4 gather + red.global.add.v4.f32 scatter
// ---------------------------------------------------------------------------
__global__ void edge_agg_kernel(const void* __restrict__ ei,
                                const float* __restrict__ H,
                                float* __restrict__ out, int E, int n) {
    long long t = (long long)blockIdx.x * blockDim.x + threadIdx.x;
    int idx  = (int)(t >> 4);
    int lane = (int)(t & 15);
    int e2 = E + n;
    if (idx >= e2) return;
    bool is64 = (g_is64 != 0);
    int src, dst;
    load_edge(ei, idx, E, n, is64, src, dst);
    float alpha = g_w[idx] / (g_s[dst] + 1e-16f);
    float4 hv = __ldg((const float4*)(H + (size_t)src * F) + lane);
    float* p = out + (size_t)dst * F + lane * 4;
    asm volatile("red.global.add.v4.f32 [%0], {%1,%2,%3,%4};"
                 :: "l"(p), "f"(hv.x * alpha), "f"(hv.y * alpha),
                    "f"(hv.z * alpha), "f"(hv.w * alpha)
                 : "memory");
}

// ---------------------------------------------------------------------------
extern "C" void kernel_launch(void* const* d_in, const int* in_sizes, int n_in,
                              void* d_out, int out_size) {
    const float* x   = (const float*)d_in[0];
    const void*  ei  = d_in[1];
    const float* W1  = (const float*)d_in[2];
    const float* as1 = (const float*)d_in[3];
    const float* ad1 = (const float*)d_in[4];
    const float* b1  = (const float*)d_in[5];
    const float* W2  = (const float*)d_in[6];
    const float* as2 = (const float*)d_in[7];
    const float* ad2 = (const float*)d_in[8];
    const float* b2  = (const float*)d_in[9];
    float* out = (float*)d_out;

    const int N  = in_sizes[0] / 128;
    const int E  = in_sizes[1] / 2;
    const int E2 = E + N;

    float *p_h, *p_x1, *p_asrc, *p_adst;
    cudaGetSymbolAddress((void**)&p_h,    g_h);
    cudaGetSymbolAddress((void**)&p_x1,   g_x1);
    cudaGetSymbolAddress((void**)&p_asrc, g_asrc);
    cudaGetSymbolAddress((void**)&p_adst, g_adst);

    const int TB = 256;
    dim3 gInit((N * F + TB - 1) / TB);
    dim3 gGemm((N + 63) / 64);
    dim3 gEA((E2 + TB - 1) / TB);
    long long tB = (long long)E2 * 16;
    dim3 gEB((unsigned)((tB + TB - 1) / TB));

    detect_kernel<<<1, 1>>>((const int*)ei);

    // ---- Layer 1 ----
    init_kernel<<<gInit, TB>>>(p_x1, b1, N);   // x1 = b1 broadcast, s = 0
    gemm_att_kernel<128, false><<<gGemm, TB>>>(x, W1, as1, ad1, p_h, p_asrc, p_adst, N);
    edge_attn_kernel<<<gEA, TB>>>(ei, E, N);
    edge_agg_kernel<<<gEB, TB>>>(ei, p_h, p_x1, E, N);   // x1 += alpha*h (pre-relu)

    // ---- Layer 2 ----
    init_kernel<<<gInit, TB>>>(out, b2, N);    // out = b2 broadcast, s = 0
    gemm_att_kernel<64, true><<<gGemm, TB>>>(p_x1, W2, as2, ad2, p_h, p_asrc, p_adst, N);
    edge_attn_kernel<<<gEA, TB>>>(ei, E, N);
    edge_agg_kernel<<<gEB, TB>>>(ei, p_h, out, E, N);
}

// round 14
// speedup vs baseline: 1.0303x; 1.0303x over previous
#include <cuda_runtime.h>
#include <math.h>

#define F 64
#define NEG 0.2f

static const int NMAX  = 50000;
static const int EMAX  = 800000;
static const int E2MAX = NMAX + EMAX;

// Scratch (allocation-free: __device__ globals)
__device__ __align__(128) float g_h [NMAX * F];   // h of current layer
__device__ __align__(128) float g_x1[NMAX * F];   // layer-1 output (pre-relu, bias added)
__device__ __align__(128) float g_asrc[NMAX];
__device__ __align__(128) float g_adst[NMAX];
__device__ __align__(128) float g_s[NMAX];
__device__ __align__(128) float g_w[E2MAX];
__device__ int g_is64;

// ---------------------------------------------------------------------------
// Detect whether edge_index is int64 or int32 (JAX x64-default ambiguity).
// In int64 little-endian, every odd int32 word of nonneg indices is 0.
// ---------------------------------------------------------------------------
__global__ void detect_kernel(const int* __restrict__ ei32) {
    if (blockIdx.x == 0 && threadIdx.x == 0) {
        int nz = 0;
        #pragma unroll 8
        for (int i = 0; i < 64; i++) nz += (ei32[2 * i + 1] != 0);
        g_is64 = (nz == 0) ? 1 : 0;
    }
}

__device__ __forceinline__ void load_edge(const void* ei, int idx, int E, int n,
                                          bool is64, int& src, int& dst) {
    if (idx < E) {
        if (is64) {
            const long long* p = (const long long*)ei;
            src = (int)p[idx];
            dst = (int)p[E + idx];
        } else {
            const int* p = (const int*)ei;
            src = p[idx];
            dst = p[E + idx];
        }
    } else {
        src = dst = idx - E;   // self loop
    }
}

// ---------------------------------------------------------------------------
// init: out[node][c] = bias[c]; s[node] = 0
// ---------------------------------------------------------------------------
__global__ void init_kernel(float* __restrict__ out, const float* __restrict__ bias, int n) {
    int idx = blockIdx.x * blockDim.x + threadIdx.x;
    if (idx < n * F) out[idx] = bias[idx & (F - 1)];
    if (idx < n) g_s[idx] = 0.f;
}

// ---------------------------------------------------------------------------
// Fused GEMM + attention scores.
// Block: 64 nodes x 64 cols, 256 threads, 4x4 register tile per thread.
// Xs padded stride K+4 (= 4 mod 32) -> conflict-free x broadcasts.
// Epilogue: h store + per-node dot with att_src/att_dst via 16-lane shfl reduce.
// ---------------------------------------------------------------------------
template<int K, bool RELU>
__global__ void __launch_bounds__(256) gemm_att_kernel(
    const float* __restrict__ X, const float* __restrict__ Wm,
    const float* __restrict__ att_s, const float* __restrict__ att_d,
    float* __restrict__ H, float* __restrict__ asrc, float* __restrict__ adst,
    int n)
{
    constexpr int XS = K + 4;
    __shared__ float Xs[64 * XS];
    __shared__ float Ws[32 * F];

    const int tid = threadIdx.x;
    const int nb  = blockIdx.x * 64;

    // Stage X tile (full K), vectorized + coalesced
    constexpr int K4 = K / 4;
    for (int i = tid; i < 64 * K4; i += 256) {
        int node = i / K4;
        int k4   = i - node * K4;
        int gn   = nb + node;
        float4 v = make_float4(0.f, 0.f, 0.f, 0.f);
        if (gn < n) {
            v = __ldg((const float4*)(X + (size_t)gn * K) + k4);
            if (RELU) {
                v.x = fmaxf(v.x, 0.f); v.y = fmaxf(v.y, 0.f);
                v.z = fmaxf(v.z, 0.f); v.w = fmaxf(v.w, 0.f);
            }
        }
        *(float4*)(Xs + node * XS + k4 * 4) = v;
    }

    const int cg = tid & 15, ng = tid >> 4;
    const int c0 = cg * 4, n0 = ng * 4;

    float acc[4][4];
    #pragma unroll
    for (int i = 0; i < 4; i++)
        #pragma unroll
        for (int j = 0; j < 4; j++) acc[i][j] = 0.f;

    for (int kt = 0; kt < K; kt += 32) {
        __syncthreads();                       // Xs staged / prev tile consumed
        for (int i = tid; i < 32 * F / 4; i += 256)
            ((float4*)Ws)[i] = __ldg((const float4*)(Wm + (size_t)kt * F) + i);
        __syncthreads();

        #pragma unroll
        for (int kk = 0; kk < 32; kk++) {
            float4 wv = *(const float4*)(Ws + kk * F + c0);
            int k = kt + kk;
            float x0 = Xs[(n0 + 0) * XS + k];
            float x1 = Xs[(n0 + 1) * XS + k];
            float x2 = Xs[(n0 + 2) * XS + k];
            float x3 = Xs[(n0 + 3) * XS + k];
            acc[0][0] += x0 * wv.x; acc[0][1] += x0 * wv.y; acc[0][2] += x0 * wv.z; acc[0][3] += x0 * wv.w;
            acc[1][0] += x1 * wv.x; acc[1][1] += x1 * wv.y; acc[1][2] += x1 * wv.z; acc[1][3] += x1 * wv.w;
            acc[2][0] += x2 * wv.x; acc[2][1] += x2 * wv.y; acc[2][2] += x2 * wv.z; acc[2][3] += x2 * wv.w;
            acc[3][0] += x3 * wv.x; acc[3][1] += x3 * wv.y; acc[3][2] += x3 * wv.z; acc[3][3] += x3 * wv.w;
        }
    }

    // Epilogue: store h, fused attention dots
    float4 av = __ldg((const float4*)att_s + cg);
    float4 dv = __ldg((const float4*)att_d + cg);
    #pragma unroll
    for (int i = 0; i < 4; i++) {
        int gn = nb + n0 + i;
        float ps = acc[i][0] * av.x + acc[i][1] * av.y + acc[i][2] * av.z + acc[i][3] * av.w;
        float pd = acc[i][0] * dv.x + acc[i][1] * dv.y + acc[i][2] * dv.z + acc[i][3] * dv.w;
        #pragma unroll
        for (int off = 8; off >= 1; off >>= 1) {
            ps += __shfl_xor_sync(0xffffffffu, ps, off);
            pd += __shfl_xor_sync(0xffffffffu, pd, off);
        }
        if (gn < n) {
            *(float4*)(H + (size_t)gn * F + c0) =
                make_float4(acc[i][0], acc[i][1], acc[i][2], acc[i][3]);
            if (cg == 0) { asrc[gn] = ps; adst[gn] = pd; }
        }
    }
}

// ---------------------------------------------------------------------------
// Edge pass A: w = exp(leaky_relu(a_src[src] + a_dst[dst])); s[dst] += w
// (segment-max dropped: algebraically identical softmax, values fp32-safe)
// ---------------------------------------------------------------------------
__global__ void edge_attn_kernel(const void* __restrict__ ei, int E, int n) {
    int idx = blockIdx.x * blockDim.x + threadIdx.x;
    int e2 = E + n;
    if (idx >= e2) return;
    bool is64 = (g_is64 != 0);
    int src, dst;
    load_edge(ei, idx, E, n, is64, src, dst);
    float e = g_asrc[src] + g_adst[dst];
    e = (e > 0.f) ? e : NEG * e;
    float w = __expf(e);
    g_w[idx] = w;
    atomicAdd(&g_s[dst], w);
}

// ---------------------------------------------------------------------------
// Edge pass B: out[dst][:] += (w/(s[dst]+eps)) * h[src][:]
// Half-warp (16 lanes) per edge, float4 gather + red.global.add.v4.f32 scatter
// ---------------------------------------------------------------------------
__global__ void edge_agg_kernel(const void* __restrict__ ei,
                                const float* __restrict__ H,
                                float* __restrict__ out, int E, int n) {
    long long t = (long long)blockIdx.x * blockDim.x + threadIdx.x;
    int idx  = (int)(t >> 4);
    int lane = (int)(t & 15);
    int e2 = E + n;
    if (idx >= e2) return;
    bool is64 = (g_is64 != 0);
    int src, dst;
    load_edge(ei, idx, E, n, is64, src, dst);
    float alpha = g_w[idx] / (g_s[dst] + 1e-16f);
    float4 hv = __ldg((const float4*)(H + (size_t)src * F) + lane);
    float* p = out + (size_t)dst * F + lane * 4;
    asm volatile("red.global.add.v4.f32 [%0], {%1,%2,%3,%4};"
                 :: "l"(p), "f"(hv.x * alpha), "f"(hv.y * alpha),
                    "f"(hv.z * alpha), "f"(hv.w * alpha)
                 : "memory");
}

// ---------------------------------------------------------------------------
extern "C" void kernel_launch(void* const* d_in, const int* in_sizes, int n_in,
                              void* d_out, int out_size) {
    const float* x   = (const float*)d_in[0];
    const void*  ei  = d_in[1];
    const float* W1  = (const float*)d_in[2];
    const float* as1 = (const float*)d_in[3];
    const float* ad1 = (const float*)d_in[4];
    const float* b1  = (const float*)d_in[5];
    const float* W2  = (const float*)d_in[6];
    const float* as2 = (const float*)d_in[7];
    const float* ad2 = (const float*)d_in[8];
    const float* b2  = (const float*)d_in[9];
    float* out = (float*)d_out;

    const int N  = in_sizes[0] / 128;
    const int E  = in_sizes[1] / 2;
    const int E2 = E + N;

    float *p_h, *p_x1, *p_asrc, *p_adst;
    cudaGetSymbolAddress((void**)&p_h,    g_h);
    cudaGetSymbolAddress((void**)&p_x1,   g_x1);
    cudaGetSymbolAddress((void**)&p_asrc, g_asrc);
    cudaGetSymbolAddress((void**)&p_adst, g_adst);

    const int TB = 256;
    dim3 gInit((N * F + TB - 1) / TB);
    dim3 gGemm((N + 63) / 64);
    dim3 gEA((E2 + TB - 1) / TB);
    long long tB = (long long)E2 * 16;
    dim3 gEB((unsigned)((tB + TB - 1) / TB));

    detect_kernel<<<1, 1>>>((const int*)ei);

    // ---- Layer 1 ----
    init_kernel<<<gInit, TB>>>(p_x1, b1, N);   // x1 = b1 broadcast, s = 0
    gemm_att_kernel<128, false><<<gGemm, TB>>>(x, W1, as1, ad1, p_h, p_asrc, p_adst, N);
    edge_attn_kernel<<<gEA, TB>>>(ei, E, N);
    edge_agg_kernel<<<gEB, TB>>>(ei, p_h, p_x1, E, N);   // x1 += alpha*h (pre-relu)

    // ---- Layer 2 ----
    init_kernel<<<gInit, TB>>>(out, b2, N);    // out = b2 broadcast, s = 0
    gemm_att_kernel<64, true><<<gGemm, TB>>>(p_x1, W2, as2, ad2, p_h, p_asrc, p_adst, N);
    edge_attn_kernel<<<gEA, TB>>>(ei, E, N);
    edge_agg_kernel<<<gEB, TB>>>(ei, p_h, out, E, N);
}

// round 15
// speedup vs baseline: 1.0319x; 1.0015x over previous
#include <cuda_runtime.h>
#include <math.h>

#define F 64
#define NEG 0.2f

static const int NMAX  = 50000;
static const int EMAX  = 800000;
static const int E2MAX = NMAX + EMAX;

// Scratch (allocation-free: __device__ globals)
__device__ __align__(128) float g_h [NMAX * F];   // h of current layer
__device__ __align__(128) float g_x1[NMAX * F];   // layer-1 output (pre-relu, bias added)
__device__ __align__(128) float g_asrc[NMAX];
__device__ __align__(128) float g_adst[NMAX];
__device__ __align__(128) float g_s[NMAX];
__device__ __align__(128) float g_w[E2MAX];
__device__ int g_is64;

// ---------------------------------------------------------------------------
// Detect whether edge_index is int64 or int32 (JAX x64-default ambiguity).
// In int64 little-endian, every odd int32 word of nonneg indices is 0.
// ---------------------------------------------------------------------------
__global__ void detect_kernel(const int* __restrict__ ei32) {
    if (blockIdx.x == 0 && threadIdx.x == 0) {
        int nz = 0;
        #pragma unroll 8
        for (int i = 0; i < 64; i++) nz += (ei32[2 * i + 1] != 0);
        g_is64 = (nz == 0) ? 1 : 0;
    }
}

__device__ __forceinline__ void load_edge(const void* ei, int idx, int E, int n,
                                          bool is64, int& src, int& dst) {
    if (idx < E) {
        if (is64) {
            const long long* p = (const long long*)ei;
            src = (int)p[idx];
            dst = (int)p[E + idx];
        } else {
            const int* p = (const int*)ei;
            src = p[idx];
            dst = p[E + idx];
        }
    } else {
        src = dst = idx - E;   // self loop
    }
}

// ---------------------------------------------------------------------------
// init: out[node][c] = bias[c]; s[node] = 0
// ---------------------------------------------------------------------------
__global__ void init_kernel(float* __restrict__ out, const float* __restrict__ bias, int n) {
    int idx = blockIdx.x * blockDim.x + threadIdx.x;
    if (idx < n * F) out[idx] = bias[idx & (F - 1)];
    if (idx < n) g_s[idx] = 0.f;
}

// ---------------------------------------------------------------------------
// Fused GEMM + attention scores.
// Block: 64 nodes x 64 cols, 256 threads, 4x4 register tile per thread.
// Xs padded stride K+4 (= 4 mod 32) -> conflict-free x broadcasts.
// Epilogue: h store + per-node dot with att_src/att_dst via 16-lane shfl reduce.
// ---------------------------------------------------------------------------
template<int K, bool RELU>
__global__ void __launch_bounds__(256) gemm_att_kernel(
    const float* __restrict__ X, const float* __restrict__ Wm,
    const float* __restrict__ att_s, const float* __restrict__ att_d,
    float* __restrict__ H, float* __restrict__ asrc, float* __restrict__ adst,
    int n)
{
    constexpr int XS = K + 4;
    __shared__ float Xs[64 * XS];
    __shared__ float Ws[32 * F];

    const int tid = threadIdx.x;
    const int nb  = blockIdx.x * 64;

    // Stage X tile (full K), vectorized + coalesced
    constexpr int K4 = K / 4;
    for (int i = tid; i < 64 * K4; i += 256) {
        int node = i / K4;
        int k4   = i - node * K4;
        int gn   = nb + node;
        float4 v = make_float4(0.f, 0.f, 0.f, 0.f);
        if (gn < n) {
            v = __ldg((const float4*)(X + (size_t)gn * K) + k4);
            if (RELU) {
                v.x = fmaxf(v.x, 0.f); v.y = fmaxf(v.y, 0.f);
                v.z = fmaxf(v.z, 0.f); v.w = fmaxf(v.w, 0.f);
            }
        }
        *(float4*)(Xs + node * XS + k4 * 4) = v;
    }

    const int cg = tid & 15, ng = tid >> 4;
    const int c0 = cg * 4, n0 = ng * 4;

    float acc[4][4];
    #pragma unroll
    for (int i = 0; i < 4; i++)
        #pragma unroll
        for (int j = 0; j < 4; j++) acc[i][j] = 0.f;

    for (int kt = 0; kt < K; kt += 32) {
        __syncthreads();                       // Xs staged / prev tile consumed
        for (int i = tid; i < 32 * F / 4; i += 256)
            ((float4*)Ws)[i] = __ldg((const float4*)(Wm + (size_t)kt * F) + i);
        __syncthreads();

        #pragma unroll
        for (int kk = 0; kk < 32; kk++) {
            float4 wv = *(const float4*)(Ws + kk * F + c0);
            int k = kt + kk;
            float x0 = Xs[(n0 + 0) * XS + k];
            float x1 = Xs[(n0 + 1) * XS + k];
            float x2 = Xs[(n0 + 2) * XS + k];
            float x3 = Xs[(n0 + 3) * XS + k];
            acc[0][0] += x0 * wv.x; acc[0][1] += x0 * wv.y; acc[0][2] += x0 * wv.z; acc[0][3] += x0 * wv.w;
            acc[1][0] += x1 * wv.x; acc[1][1] += x1 * wv.y; acc[1][2] += x1 * wv.z; acc[1][3] += x1 * wv.w;
            acc[2][0] += x2 * wv.x; acc[2][1] += x2 * wv.y; acc[2][2] += x2 * wv.z; acc[2][3] += x2 * wv.w;
            acc[3][0] += x3 * wv.x; acc[3][1] += x3 * wv.y; acc[3][2] += x3 * wv.z; acc[3][3] += x3 * wv.w;
        }
    }

    // Epilogue: store h, fused attention dots
    float4 av = __ldg((const float4*)att_s + cg);
    float4 dv = __ldg((const float4*)att_d + cg);
    #pragma unroll
    for (int i = 0; i < 4; i++) {
        int gn = nb + n0 + i;
        float ps = acc[i][0] * av.x + acc[i][1] * av.y + acc[i][2] * av.z + acc[i][3] * av.w;
        float pd = acc[i][0] * dv.x + acc[i][1] * dv.y + acc[i][2] * dv.z + acc[i][3] * dv.w;
        #pragma unroll
        for (int off = 8; off >= 1; off >>= 1) {
            ps += __shfl_xor_sync(0xffffffffu, ps, off);
            pd += __shfl_xor_sync(0xffffffffu, pd, off);
        }
        if (gn < n) {
            *(float4*)(H + (size_t)gn * F + c0) =
                make_float4(acc[i][0], acc[i][1], acc[i][2], acc[i][3]);
            if (cg == 0) { asrc[gn] = ps; adst[gn] = pd; }
        }
    }
}

// ---------------------------------------------------------------------------
// Edge pass A: w = exp(leaky_relu(a_src[src] + a_dst[dst])); s[dst] += w
// (segment-max dropped: algebraically identical softmax, values fp32-safe)
// ---------------------------------------------------------------------------
__global__ void edge_attn_kernel(const void* __restrict__ ei, int E, int n) {
    int idx = blockIdx.x * blockDim.x + threadIdx.x;
    int e2 = E + n;
    if (idx >= e2) return;
    bool is64 = (g_is64 != 0);
    int src, dst;
    load_edge(ei, idx, E, n, is64, src, dst);
    float e = g_asrc[src] + g_adst[dst];
    e = (e > 0.f) ? e : NEG * e;
    float w = __expf(e);
    g_w[idx] = w;
    atomicAdd(&g_s[dst], w);
}

// ---------------------------------------------------------------------------
// Edge pass B: out[dst][:] += (w/(s[dst]+eps)) * h[src][:]
// Half-warp (16 lanes) per edge, float4 gather + red.global.add.v4.f32 scatter
// ---------------------------------------------------------------------------
__global__ void edge_agg_kernel(const void* __restrict__ ei,
                                const float* __restrict__ H,
                                float* __restrict__ out, int E, int n) {
    long long t = (long long)blockIdx.x * blockDim.x + threadIdx.x;
    int idx  = (int)(t >> 4);
    int lane = (int)(t & 15);
    int e2 = E + n;
    if (idx >= e2) return;
    bool is64 = (g_is64 != 0);
    int src, dst;
    load_edge(ei, idx, E, n, is64, src, dst);
    float alpha = g_w[idx] / (g_s[dst] + 1e-16f);
    float4 hv = __ldg((const float4*)(H + (size_t)src * F) + lane);
    float* p = out + (size_t)dst * F + lane * 4;
    asm volatile("red.global.add.v4.f32 [%0], {%1,%2,%3,%4};"
                 :: "l"(p), "f"(hv.x * alpha), "f"(hv.y * alpha),
                    "f"(hv.z * alpha), "f"(hv.w * alpha)
                 : "memory");
}

// ---------------------------------------------------------------------------
extern "C" void kernel_launch(void* const* d_in, const int* in_sizes, int n_in,
                              void* d_out, int out_size) {
    const float* x   = (const float*)d_in[0];
    const void*  ei  = d_in[1];
    const float* W1  = (const float*)d_in[2];
    const float* as1 = (const float*)d_in[3];
    const float* ad1 = (const float*)d_in[4];
    const float* b1  = (const float*)d_in[5];
    const float* W2  = (const float*)d_in[6];
    const float* as2 = (const float*)d_in[7];
    const float* ad2 = (const float*)d_in[8];
    const float* b2  = (const float*)d_in[9];
    float* out = (float*)d_out;

    const int N  = in_sizes[0] / 128;
    const int E  = in_sizes[1] / 2;
    const int E2 = E + N;

    float *p_h, *p_x1, *p_asrc, *p_adst;
    cudaGetSymbolAddress((void**)&p_h,    g_h);
    cudaGetSymbolAddress((void**)&p_x1,   g_x1);
    cudaGetSymbolAddress((void**)&p_asrc, g_asrc);
    cudaGetSymbolAddress((void**)&p_adst, g_adst);

    const int TB = 256;
    dim3 gInit((N * F + TB - 1) / TB);
    dim3 gGemm((N + 63) / 64);
    dim3 gEA((E2 + TB - 1) / TB);
    long long tB = (long long)E2 * 16;
    dim3 gEB((unsigned)((tB + TB - 1) / TB));

    detect_kernel<<<1, 1>>>((const int*)ei);

    // ---- Layer 1 ----
    init_kernel<<<gInit, TB>>>(p_x1, b1, N);   // x1 = b1 broadcast, s = 0
    gemm_att_kernel<128, false><<<gGemm, TB>>>(x, W1, as1, ad1, p_h, p_asrc, p_adst, N);
    edge_attn_kernel<<<gEA, TB>>>(ei, E, N);
    edge_agg_kernel<<<gEB, TB>>>(ei, p_h, p_x1, E, N);   // x1 += alpha*h (pre-relu)

    // ---- Layer 2 ----
    init_kernel<<<gInit, TB>>>(out, b2, N);    // out = b2 broadcast, s = 0
    gemm_att_kernel<64, true><<<gGemm, TB>>>(p_x1, W2, as2, ad2, p_h, p_asrc, p_adst, N);
    edge_attn_kernel<<<gEA, TB>>>(ei, E, N);
    edge_agg_kernel<<<gEB, TB>>>(ei, p_h, out, E, N);
}

// round 16
// speedup vs baseline: 1.0412x; 1.0090x over previous
#include <cuda_runtime.h>
#include <math.h>

#define F 64
#define NEG 0.2f

static const int NMAX  = 50000;
static const int EMAX  = 800000;
static const int E2MAX = NMAX + EMAX;

// Scratch (allocation-free: __device__ globals)
__device__ __align__(128) float g_h [NMAX * F];   // h of current layer
__device__ __align__(128) float g_x1[NMAX * F];   // layer-1 output (pre-relu, bias added)
__device__ __align__(128) float g_asrc[NMAX];
__device__ __align__(128) float g_adst[NMAX];
__device__ __align__(128) float g_s[NMAX];
__device__ __align__(128) float g_w[E2MAX];
__device__ int g_is64;

// ---------------------------------------------------------------------------
// Detect whether edge_index is int64 or int32 (JAX x64-default ambiguity).
// In int64 little-endian, every odd int32 word of nonneg indices is 0.
// ---------------------------------------------------------------------------
__global__ void detect_kernel(const int* __restrict__ ei32) {
    if (blockIdx.x == 0 && threadIdx.x == 0) {
        int nz = 0;
        #pragma unroll 8
        for (int i = 0; i < 64; i++) nz += (ei32[2 * i + 1] != 0);
        g_is64 = (nz == 0) ? 1 : 0;
    }
}

__device__ __forceinline__ void load_edge(const void* ei, int idx, int E, int n,
                                          bool is64, int& src, int& dst) {
    if (idx < E) {
        if (is64) {
            const long long* p = (const long long*)ei;
            src = (int)p[idx];
            dst = (int)p[E + idx];
        } else {
            const int* p = (const int*)ei;
            src = p[idx];
            dst = p[E + idx];
        }
    } else {
        src = dst = idx - E;   // self loop
    }
}

// ---------------------------------------------------------------------------
// init: out[node][c] = bias[c]; s[node] = 0
// ---------------------------------------------------------------------------
__global__ void init_kernel(float* __restrict__ out, const float* __restrict__ bias, int n) {
    int idx = blockIdx.x * blockDim.x + threadIdx.x;
    if (idx < n * F) out[idx] = bias[idx & (F - 1)];
    if (idx < n) g_s[idx] = 0.f;
}

// ---------------------------------------------------------------------------
// Fused GEMM + attention scores.
// Block: 64 nodes x 64 cols, 256 threads, 4x4 register tile per thread.
// Xs padded stride K+4 (= 4 mod 32) -> conflict-free x broadcasts.
// Epilogue: h store + per-node dot with att_src/att_dst via 16-lane shfl reduce.
// ---------------------------------------------------------------------------
template<int K, bool RELU>
__global__ void __launch_bounds__(256) gemm_att_kernel(
    const float* __restrict__ X, const float* __restrict__ Wm,
    const float* __restrict__ att_s, const float* __restrict__ att_d,
    float* __restrict__ H, float* __restrict__ asrc, float* __restrict__ adst,
    int n)
{
    constexpr int XS = K + 4;
    __shared__ float Xs[64 * XS];
    __shared__ float Ws[32 * F];

    const int tid = threadIdx.x;
    const int nb  = blockIdx.x * 64;

    // Stage X tile (full K), vectorized + coalesced
    constexpr int K4 = K / 4;
    for (int i = tid; i < 64 * K4; i += 256) {
        int node = i / K4;
        int k4   = i - node * K4;
        int gn   = nb + node;
        float4 v = make_float4(0.f, 0.f, 0.f, 0.f);
        if (gn < n) {
            v = __ldg((const float4*)(X + (size_t)gn * K) + k4);
            if (RELU) {
                v.x = fmaxf(v.x, 0.f); v.y = fmaxf(v.y, 0.f);
                v.z = fmaxf(v.z, 0.f); v.w = fmaxf(v.w, 0.f);
            }
        }
        *(float4*)(Xs + node * XS + k4 * 4) = v;
    }

    const int cg = tid & 15, ng = tid >> 4;
    const int c0 = cg * 4, n0 = ng * 4;

    float acc[4][4];
    #pragma unroll
    for (int i = 0; i < 4; i++)
        #pragma unroll
        for (int j = 0; j < 4; j++) acc[i][j] = 0.f;

    for (int kt = 0; kt < K; kt += 32) {
        __syncthreads();                       // Xs staged / prev tile consumed
        for (int i = tid; i < 32 * F / 4; i += 256)
            ((float4*)Ws)[i] = __ldg((const float4*)(Wm + (size_t)kt * F) + i);
        __syncthreads();

        #pragma unroll
        for (int kk = 0; kk < 32; kk++) {
            float4 wv = *(const float4*)(Ws + kk * F + c0);
            int k = kt + kk;
            float x0 = Xs[(n0 + 0) * XS + k];
            float x1 = Xs[(n0 + 1) * XS + k];
            float x2 = Xs[(n0 + 2) * XS + k];
            float x3 = Xs[(n0 + 3) * XS + k];
            acc[0][0] += x0 * wv.x; acc[0][1] += x0 * wv.y; acc[0][2] += x0 * wv.z; acc[0][3] += x0 * wv.w;
            acc[1][0] += x1 * wv.x; acc[1][1] += x1 * wv.y; acc[1][2] += x1 * wv.z; acc[1][3] += x1 * wv.w;
            acc[2][0] += x2 * wv.x; acc[2][1] += x2 * wv.y; acc[2][2] += x2 * wv.z; acc[2][3] += x2 * wv.w;
            acc[3][0] += x3 * wv.x; acc[3][1] += x3 * wv.y; acc[3][2] += x3 * wv.z; acc[3][3] += x3 * wv.w;
        }
    }

    // Epilogue: store h, fused attention dots
    float4 av = __ldg((const float4*)att_s + cg);
    float4 dv = __ldg((const float4*)att_d + cg);
    #pragma unroll
    for (int i = 0; i < 4; i++) {
        int gn = nb + n0 + i;
        float ps = acc[i][0] * av.x + acc[i][1] * av.y + acc[i][2] * av.z + acc[i][3] * av.w;
        float pd = acc[i][0] * dv.x + acc[i][1] * dv.y + acc[i][2] * dv.z + acc[i][3] * dv.w;
        #pragma unroll
        for (int off = 8; off >= 1; off >>= 1) {
            ps += __shfl_xor_sync(0xffffffffu, ps, off);
            pd += __shfl_xor_sync(0xffffffffu, pd, off);
        }
        if (gn < n) {
            *(float4*)(H + (size_t)gn * F + c0) =
                make_float4(acc[i][0], acc[i][1], acc[i][2], acc[i][3]);
            if (cg == 0) { asrc[gn] = ps; adst[gn] = pd; }
        }
    }
}

// ---------------------------------------------------------------------------
// Edge pass A: w = exp(leaky_relu(a_src[src] + a_dst[dst])); s[dst] += w
// (segment-max dropped: algebraically identical softmax, values fp32-safe)
// ---------------------------------------------------------------------------
__global__ void edge_attn_kernel(const void* __restrict__ ei, int E, int n) {
    int idx = blockIdx.x * blockDim.x + threadIdx.x;
    int e2 = E + n;
    if (idx >= e2) return;
    bool is64 = (g_is64 != 0);
    int src, dst;
    load_edge(ei, idx, E, n, is64, src, dst);
    float e = g_asrc[src] + g_adst[dst];
    e = (e > 0.f) ? e : NEG * e;
    float w = __expf(e);
    g_w[idx] = w;
    atomicAdd(&g_s[dst], w);
}

// ---------------------------------------------------------------------------
// Edge pass B: out[dst][:] += (w/(s[dst]+eps)) * h[src][:]
// Half-warp (16 lanes) per edge, float4 gather + red.global.add.v4.f32 scatter
// ---------------------------------------------------------------------------
__global__ void edge_agg_kernel(const void* __restrict__ ei,
                                const float* __restrict__ H,
                                float* __restrict__ out, int E, int n) {
    long long t = (long long)blockIdx.x * blockDim.x + threadIdx.x;
    int idx  = (int)(t >> 4);
    int lane = (int)(t & 15);
    int e2 = E + n;
    if (idx >= e2) return;
    bool is64 = (g_is64 != 0);
    int src, dst;
    load_edge(ei, idx, E, n, is64, src, dst);
    float alpha = g_w[idx] / (g_s[dst] + 1e-16f);
    float4 hv = __ldg((const float4*)(H + (size_t)src * F) + lane);
    float* p = out + (size_t)dst * F + lane * 4;
    asm volatile("red.global.add.v4.f32 [%0], {%1,%2,%3,%4};"
                 :: "l"(p), "f"(hv.x * alpha), "f"(hv.y * alpha),
                    "f"(hv.z * alpha), "f"(hv.w * alpha)
                 : "memory");
}

// ---------------------------------------------------------------------------
extern "C" void kernel_launch(void* const* d_in, const int* in_sizes, int n_in,
                              void* d_out, int out_size) {
    const float* x   = (const float*)d_in[0];
    const void*  ei  = d_in[1];
    const float* W1  = (const float*)d_in[2];
    const float* as1 = (const float*)d_in[3];
    const float* ad1 = (const float*)d_in[4];
    const float* b1  = (const float*)d_in[5];
    const float* W2  = (const float*)d_in[6];
    const float* as2 = (const float*)d_in[7];
    const float* ad2 = (const float*)d_in[8];
    const float* b2  = (const float*)d_in[9];
    float* out = (float*)d_out;

    const int N  = in_sizes[0] / 128;
    const int E  = in_sizes[1] / 2;
    const int E2 = E + N;

    float *p_h, *p_x1, *p_asrc, *p_adst;
    cudaGetSymbolAddress((void**)&p_h,    g_h);
    cudaGetSymbolAddress((void**)&p_x1,   g_x1);
    cudaGetSymbolAddress((void**)&p_asrc, g_asrc);
    cudaGetSymbolAddress((void**)&p_adst, g_adst);

    const int TB = 256;
    dim3 gInit((N * F + TB - 1) / TB);
    dim3 gGemm((N + 63) / 64);
    dim3 gEA((E2 + TB - 1) / TB);
    long long tB = (long long)E2 * 16;
    dim3 gEB((unsigned)((tB + TB - 1) / TB));

    detect_kernel<<<1, 1>>>((const int*)ei);

    // ---- Layer 1 ----
    init_kernel<<<gInit, TB>>>(p_x1, b1, N);   // x1 = b1 broadcast, s = 0
    gemm_att_kernel<128, false><<<gGemm, TB>>>(x, W1, as1, ad1, p_h, p_asrc, p_adst, N);
    edge_attn_kernel<<<gEA, TB>>>(ei, E, N);
    edge_agg_kernel<<<gEB, TB>>>(ei, p_h, p_x1, E, N);   // x1 += alpha*h (pre-relu)

    // ---- Layer 2 ----
    init_kernel<<<gInit, TB>>>(out, b2, N);    // out = b2 broadcast, s = 0
    gemm_att_kernel<64, true><<<gGemm, TB>>>(p_x1, W2, as2, ad2, p_h, p_asrc, p_adst, N);
    edge_attn_kernel<<<gEA, TB>>>(ei, E, N);
    edge_agg_kernel<<<gEB, TB>>>(ei, p_h, out, E, N);
}